// round 2
// baseline (speedup 1.0000x reference)
#include <cuda_runtime.h>

#define BATCH  128
#define TSTEPS 512
#define FEAT   64
#define UN1    256
#define UN2    128

// ---------------- scratch (static device globals; allocation-free at launch) ----
__device__ float g_xw1[(size_t)BATCH * TSTEPS * 4 * UN1];        // [b][t][1024] = x@W1+b1
__device__ float g_hseq1[(size_t)(TSTEPS + 1) * BATCH * UN1];    // [t+1][b][256], slot0 = h_{-1}=0
__device__ float g_xw2[(size_t)TSTEPS * BATCH * 4 * UN2];        // [t][b][512]  = h1@W2+b2
__device__ float g_hseq2[(size_t)(TSTEPS + 1) * BATCH * UN2];    // [t+1][b][128]
__device__ unsigned g_bar1 = 0, g_exit1 = 0, g_bar2 = 0, g_exit2 = 0;

// ---------------- feed-forward GEMM: C[M,N] = A[M,K] @ W[K,N] + bias[N] --------
// 64x64 tile, 256 threads, 4x4 per-thread register tile. All dims multiples of 64.
template <int PHASE>
__global__ void __launch_bounds__(256)
gemm_bias(const float* __restrict__ Ain, const float* __restrict__ W,
          const float* __restrict__ bias, int M, int N, int K) {
  const float* A = (PHASE == 1) ? Ain : (g_hseq1 + BATCH * UN1);  // phase2: rows (t,b) of h1
  float* C       = (PHASE == 1) ? g_xw1 : g_xw2;

  __shared__ float sA[64][68];  // [k][m] (transposed)
  __shared__ float sW[64][68];  // [k][n]

  const int n0 = blockIdx.x * 64;
  const int m0 = blockIdx.y * 64;
  const int tid = threadIdx.x;
  const int ty = tid >> 4;      // 0..15 -> m group
  const int tx = tid & 15;      // 0..15 -> n group

  float acc[4][4] = {};

  for (int kt = 0; kt < K; kt += 64) {
    for (int i = tid; i < 64 * 64; i += 256) {
      int r = i >> 6, c = i & 63;
      sA[c][r] = A[(size_t)(m0 + r) * K + kt + c];        // coalesced over k
      sW[r][c] = W[(size_t)(kt + r) * N + n0 + c];        // coalesced over n
    }
    __syncthreads();
#pragma unroll 8
    for (int k = 0; k < 64; k++) {
      float4 a = *(const float4*)&sA[k][ty * 4];
      float4 w = *(const float4*)&sW[k][tx * 4];
      acc[0][0] += a.x * w.x; acc[0][1] += a.x * w.y; acc[0][2] += a.x * w.z; acc[0][3] += a.x * w.w;
      acc[1][0] += a.y * w.x; acc[1][1] += a.y * w.y; acc[1][2] += a.y * w.z; acc[1][3] += a.y * w.w;
      acc[2][0] += a.z * w.x; acc[2][1] += a.z * w.y; acc[2][2] += a.z * w.z; acc[2][3] += a.z * w.w;
      acc[3][0] += a.w * w.x; acc[3][1] += a.w * w.y; acc[3][2] += a.w * w.z; acc[3][3] += a.w * w.w;
    }
    __syncthreads();
  }

  float4 bv = *(const float4*)&bias[n0 + tx * 4];
#pragma unroll
  for (int i = 0; i < 4; i++) {
    float4 o;
    o.x = acc[i][0] + bv.x; o.y = acc[i][1] + bv.y;
    o.z = acc[i][2] + bv.z; o.w = acc[i][3] + bv.w;
    *(float4*)&C[(size_t)(m0 + ty * 4 + i) * N + n0 + tx * 4] = o;
  }
}

// ---------------- persistent recurrent layer -----------------------------------
// LAYER==1: UNITS=256, NCTA=128 (4 batch-groups x 32 unit-groups)
// LAYER==2: UNITS=128, NCTA=64  (4 batch-groups x 16 unit-groups), writes d_out
// Per CTA: 32 batches x 8 units (=> 32 z-columns spanning the 4 gates).
// One software grid barrier per timestep; h history double-buffered via hseq[t].
template <int LAYER>
__global__ void __launch_bounds__(256)
lstm_rec(float* __restrict__ out_last) {
  constexpr int UNITS = (LAYER == 1) ? UN1 : UN2;
  constexpr int NCTA  = (LAYER == 1) ? 128 : 64;
  constexpr int UG    = NCTA / 4;          // unit groups
  constexpr int UPC   = UNITS / UG;        // 8 units per CTA
  constexpr size_t XB_STR = (LAYER == 1) ? (size_t)TSTEPS * 4 * UN1 : (size_t)4 * UN2;
  constexpr size_t XT_STR = (LAYER == 1) ? (size_t)4 * UN1 : (size_t)BATCH * 4 * UN2;

  const float* xw   = (LAYER == 1) ? g_xw1 : g_xw2;
  float* hseq       = (LAYER == 1) ? g_hseq1 : g_hseq2;
  unsigned* bar     = (LAYER == 1) ? &g_bar1 : &g_bar2;
  unsigned* exitc   = (LAYER == 1) ? &g_exit1 : &g_exit2;

  extern __shared__ float smem[];
  float* sU = smem;                 // [UNITS][32]
  float* sH = sU + UNITS * 32;      // [UNITS][34] (pad: 2-way max conflict, float2-aligned)
  float* sZ = sH + UNITS * 34;      // [32][33]

  const int tid = threadIdx.x;
  const int bg = blockIdx.x / UG;
  const int ug = blockIdx.x % UG;
  const int b0 = bg * 32;

  // U matrix passed via global pointer stored by host into constant-ish arg? No:
  // we read it from the input pointer captured in a __device__ pointer-free way —
  // instead U is passed below via out_last trick? Keep it simple: U pointer arg.
  // (see second parameter added)
  // -- placeholder, real signature below --
}

// Real recurrent kernel (with U pointer argument)
template <int LAYER>
__global__ void __launch_bounds__(256)
lstm_rec_k(const float* __restrict__ Umat, float* __restrict__ out_last) {
  constexpr int UNITS = (LAYER == 1) ? UN1 : UN2;
  constexpr int NCTA  = (LAYER == 1) ? 128 : 64;
  constexpr int UG    = NCTA / 4;
  constexpr int UPC   = UNITS / UG;                 // 8
  constexpr int C4U   = 4 * UNITS;
  constexpr size_t XB_STR = (LAYER == 1) ? (size_t)TSTEPS * 4 * UN1 : (size_t)4 * UN2;
  constexpr size_t XT_STR = (LAYER == 1) ? (size_t)4 * UN1 : (size_t)BATCH * 4 * UN2;

  const float* xw = (LAYER == 1) ? g_xw1 : g_xw2;
  float* hseq     = (LAYER == 1) ? g_hseq1 : g_hseq2;
  unsigned* bar   = (LAYER == 1) ? &g_bar1 : &g_bar2;
  unsigned* exitc = (LAYER == 1) ? &g_exit1 : &g_exit2;

  extern __shared__ float smem[];
  float* sU = smem;                 // [UNITS][32]
  float* sH = sU + UNITS * 32;      // [UNITS][34]
  float* sZ = sH + UNITS * 34;      // [32][33]

  const int tid = threadIdx.x;
  const int bg = blockIdx.x / UG;
  const int ug = blockIdx.x % UG;
  const int b0 = bg * 32;

  // load this CTA's U slice: columns = 4 gates x 8 units
  for (int i = tid; i < UNITS * 32; i += 256) {
    int k = i >> 5, cc = i & 31;
    int gate = cc >> 3, uu = cc & 7;
    sU[k * 32 + cc] = Umat[(size_t)k * C4U + gate * UNITS + ug * UPC + uu];
  }

  // per-thread cell-state ownership: (b_l, uu)
  const int b_l = tid >> 3;          // 0..31
  const int uu  = tid & 7;           // 0..7
  const int b_g = b0 + b_l;
  const int u_g = ug * UPC + uu;
  hseq[(size_t)b_g * UNITS + u_g] = 0.f;   // h_{-1} slot
  float c_reg = 0.f;

  // compute-phase mapping: 2x2 tile per thread
  const int ty = tid >> 4;           // batch pair 2*ty, 2*ty+1
  const int tx = tid & 15;           // col pair 2*tx, 2*tx+1 (never crosses a gate)
  const int cg = ((2 * tx) >> 3) * UNITS + ug * UPC + ((2 * tx) & 7);

  unsigned target = 0;
  for (int t = 0; t < TSTEPS; t++) {
    // ---- grid barrier: h writes of step t-1 (or init) visible to all CTAs ----
    target += NCTA;
    __syncthreads();
    if (tid == 0) {
      __threadfence();
      atomicAdd(bar, 1u);
      while (*(volatile unsigned*)bar < target) __nanosleep(32);
    }
    __syncthreads();

    // ---- stage h_prev slice into smem transposed [k][b] ----
    const float* hp = hseq + (size_t)t * BATCH * UNITS + (size_t)b0 * UNITS;
    for (int i = tid; i < 32 * UNITS; i += 256) {
      int bl = i / UNITS, k = i % UNITS;       // consecutive tid -> consecutive k
      sH[k * 34 + bl] = hp[(size_t)bl * UNITS + k];
    }
    __syncthreads();

    // ---- z tile: 2x2 outer-product accumulation over k ----
    const float* x0 = xw + (size_t)(b0 + 2 * ty) * XB_STR + (size_t)t * XT_STR + cg;
    float2 accA = *(const float2*)x0;
    float2 accB = *(const float2*)(x0 + XB_STR);
    const float* pH = sH + 2 * ty;
    const float* pU = sU + 2 * tx;
#pragma unroll 8
    for (int k = 0; k < UNITS; k++) {
      float2 h2 = *(const float2*)(pH + k * 34);
      float2 u2 = *(const float2*)(pU + k * 32);
      accA.x += h2.x * u2.x; accA.y += h2.x * u2.y;
      accB.x += h2.y * u2.x; accB.y += h2.y * u2.y;
    }
    sZ[(2 * ty) * 33 + 2 * tx]         = accA.x;
    sZ[(2 * ty) * 33 + 2 * tx + 1]     = accA.y;
    sZ[(2 * ty + 1) * 33 + 2 * tx]     = accB.x;
    sZ[(2 * ty + 1) * 33 + 2 * tx + 1] = accB.y;
    __syncthreads();

    // ---- gates + state update (each thread owns one (b,u)) ----
    float zi = sZ[b_l * 33 + uu];
    float zf = sZ[b_l * 33 + 8 + uu];
    float zg = sZ[b_l * 33 + 16 + uu];
    float zo = sZ[b_l * 33 + 24 + uu];
    float ig = 1.f / (1.f + __expf(-zi));
    float fg = 1.f / (1.f + __expf(-zf));
    float gg = fmaxf(zg, 0.f);
    float og = 1.f / (1.f + __expf(-zo));
    c_reg = fg * c_reg + ig * gg;
    float h = og * fmaxf(c_reg, 0.f);
    hseq[(size_t)(t + 1) * BATCH * UNITS + (size_t)b_g * UNITS + u_g] = h;
    if (LAYER == 2 && t == TSTEPS - 1)
      out_last[b_g * UN2 + u_g] = h;
  }

  // ---- exit protocol: last CTA resets counters so graph replays start clean ----
  __syncthreads();
  if (tid == 0) {
    __threadfence();
    if (atomicAdd(exitc, 1u) + 1u == (unsigned)NCTA) {
      *bar = 0u;
      *exitc = 0u;
    }
  }
}

// ---------------- launch --------------------------------------------------------
extern "C" void kernel_launch(void* const* d_in, const int* in_sizes, int n_in,
                              void* d_out, int out_size) {
  const float* x   = (const float*)d_in[0];  // [128][512][64]
  const float* W1  = (const float*)d_in[1];  // [64][1024]
  const float* U1m = (const float*)d_in[2];  // [256][1024]
  const float* b1  = (const float*)d_in[3];  // [1024]
  const float* W2  = (const float*)d_in[4];  // [256][512]
  const float* U2m = (const float*)d_in[5];  // [128][512]
  const float* b2  = (const float*)d_in[6];  // [512]
  float* out = (float*)d_out;                // [128][128]

  constexpr int SMEM1 = (UN1 * 32 + UN1 * 34 + 32 * 33) * 4;   // 71808 B
  constexpr int SMEM2 = (UN2 * 32 + UN2 * 34 + 32 * 33) * 4;   // 38016 B
  cudaFuncSetAttribute(lstm_rec_k<1>, cudaFuncAttributeMaxDynamicSharedMemorySize, SMEM1);
  cudaFuncSetAttribute(lstm_rec_k<2>, cudaFuncAttributeMaxDynamicSharedMemorySize, SMEM2);

  // K1: XW1[b][t][1024] = x(b,t,:) @ W1 + b1   (M rows are (b,t) pairs)
  gemm_bias<1><<<dim3(1024 / 64, (BATCH * TSTEPS) / 64), 256>>>(
      x, W1, b1, BATCH * TSTEPS, 4 * UN1, FEAT);

  // K2: layer-1 recurrence (persistent, 128 CTAs)
  lstm_rec_k<1><<<128, 256, SMEM1>>>(U1m, nullptr);

  // K3: XW2[t][b][512] = h1(t,b,:) @ W2 + b2   (A = g_hseq1 rows (t,b), skip slot 0)
  gemm_bias<2><<<dim3(512 / 64, (BATCH * TSTEPS) / 64), 256>>>(
      nullptr, W2, b2, BATCH * TSTEPS, 4 * UN2, UN1);

  // K4: layer-2 recurrence (persistent, 64 CTAs) -> writes final h into d_out
  lstm_rec_k<2><<<64, 256, SMEM2>>>(U2m, out);
}

// round 3
// speedup vs baseline: 1.2925x; 1.2925x over previous
#include <cuda_runtime.h>

#define BATCH  128
#define TSTEPS 512
#define FEAT   64
#define UN1    256
#define UN2    128

// ---------------- scratch (static device globals) ------------------------------
__device__ float g_xw1[(size_t)BATCH * TSTEPS * 4 * UN1];      // [b][t][1024] = x@W1 + b1
__device__ float g_hseq1[(size_t)(TSTEPS + 1) * UN1 * BATCH];  // [t][u][b], slot0 = h_{-1}=0
__device__ float g_xw2[(size_t)TSTEPS * BATCH * 4 * UN2];      // [t][b][512] = h1@W2 + b2
__device__ float g_hseq2[(size_t)(TSTEPS + 1) * UN2 * BATCH];  // [t][u][b]
__device__ unsigned g_bar1[4], g_exit1[4], g_bar2[4], g_exit2[4];  // per batch-group

// ---------------- feed-forward GEMM: C[M,N] = A[M,K] @ W[K,N] + bias[N] --------
// 64x64 tile, 256 threads, 4x4 per-thread register tile.
template <int PHASE>
__global__ void __launch_bounds__(256)
gemm_bias(const float* __restrict__ Ain, const float* __restrict__ W,
          const float* __restrict__ bias, int M, int N, int K) {
  float* C = (PHASE == 1) ? g_xw1 : g_xw2;

  __shared__ float sA[64][68];  // [k][m]
  __shared__ float sW[64][68];  // [k][n]

  const int n0 = blockIdx.x * 64;
  const int m0 = blockIdx.y * 64;
  const int tid = threadIdx.x;
  const int ty = tid >> 4;
  const int tx = tid & 15;

  float acc[4][4] = {};

  for (int kt = 0; kt < K; kt += 64) {
    if (PHASE == 1) {
      // A = x, [m=(b,t) t-minor][64], row-major
      for (int i = tid; i < 64 * 64; i += 256) {
        int r = i >> 6, c = i & 63;
        sA[c][r] = Ain[(size_t)(m0 + r) * K + kt + c];
      }
    } else {
      // A = h1 in [t][u][b] layout; m = t*128 + b (tile = one t, 64 b's)
      int t0 = m0 >> 7, bb = m0 & 127;
      const float* Ab = g_hseq1 + (size_t)(1 + t0) * UN1 * BATCH + bb;
      for (int i = tid; i < 64 * 64; i += 256) {
        int r = i & 63, c = i >> 6;                 // lanes r-consecutive: coalesced
        sA[c][r] = Ab[(size_t)(kt + c) * BATCH + r];
      }
    }
    for (int i = tid; i < 64 * 64; i += 256) {
      int r = i >> 6, c = i & 63;
      sW[r][c] = W[(size_t)(kt + r) * N + n0 + c];
    }
    __syncthreads();
#pragma unroll 8
    for (int k = 0; k < 64; k++) {
      float4 a = *(const float4*)&sA[k][ty * 4];
      float4 w = *(const float4*)&sW[k][tx * 4];
      acc[0][0] += a.x * w.x; acc[0][1] += a.x * w.y; acc[0][2] += a.x * w.z; acc[0][3] += a.x * w.w;
      acc[1][0] += a.y * w.x; acc[1][1] += a.y * w.y; acc[1][2] += a.y * w.z; acc[1][3] += a.y * w.w;
      acc[2][0] += a.z * w.x; acc[2][1] += a.z * w.y; acc[2][2] += a.z * w.z; acc[2][3] += a.z * w.w;
      acc[3][0] += a.w * w.x; acc[3][1] += a.w * w.y; acc[3][2] += a.w * w.z; acc[3][3] += a.w * w.w;
    }
    __syncthreads();
  }

  float4 bv = *(const float4*)&bias[n0 + tx * 4];
#pragma unroll
  for (int i = 0; i < 4; i++) {
    float4 o;
    o.x = acc[i][0] + bv.x; o.y = acc[i][1] + bv.y;
    o.z = acc[i][2] + bv.z; o.w = acc[i][3] + bv.w;
    *(float4*)&C[(size_t)(m0 + ty * 4 + i) * N + n0 + tx * 4] = o;
  }
}

// ---------------- persistent recurrent layer -----------------------------------
// LAYER 1: UNITS=256, 128 CTAs = 4 bg x 32 ug.  LAYER 2: UNITS=128, 64 = 4 x 16.
// CTA computes z tile [32 batches x 32 cols] (cols = 4 gates x 8 units).
// 256 threads = 8 warps; warp q handles k-slice [q*KQ, (q+1)*KQ) with 4x8
// per-thread register tiles; partials reduced through smem.
template <int LAYER>
__global__ void __launch_bounds__(256)
lstm_rec_k(const float* __restrict__ Umat, float* __restrict__ out_last) {
  constexpr int UNITS   = (LAYER == 1) ? UN1 : UN2;
  constexpr int UG      = UNITS / 8;        // unit-groups per bg = CTAs per barrier
  constexpr int KQ      = UNITS / 8;        // k per warp-slice
  constexpr int C4U     = 4 * UNITS;
  constexpr int SHS     = 36;               // sH row stride (floats)

  const float* xw = (LAYER == 1) ? g_xw1 : g_xw2;
  float* hseq     = (LAYER == 1) ? g_hseq1 : g_hseq2;
  unsigned* barA  = (LAYER == 1) ? g_bar1 : g_bar2;
  unsigned* exitA = (LAYER == 1) ? g_exit1 : g_exit2;

  extern __shared__ float smem[];
  float* sU  = smem;                        // [UNITS][32]
  float* sH  = sU + UNITS * 32;             // [UNITS][SHS]  ([k][b])
  float* sZp = sH + UNITS * SHS;            // [8][32][33] partial z

  const int tid = threadIdx.x;
  const int bg  = blockIdx.x / UG;
  const int ug  = blockIdx.x % UG;
  const int b0  = bg * 32;
  unsigned* bar   = &barA[bg];
  unsigned* exitc = &exitA[bg];

  // load this CTA's U slice: 32 cols = 4 gates x 8 units, [k][c]
  for (int i = tid; i < UNITS * 32; i += 256) {
    int k = i >> 5, cc = i & 31;
    sU[k * 32 + cc] = Umat[(size_t)k * C4U + (cc >> 3) * UNITS + ug * 8 + (cc & 7)];
  }

  // compute-phase mapping: warp q = k-slice; within warp: 4 rows x 8 cols tile
  const int q  = tid >> 5;
  const int li = tid & 31;
  const int tm = li >> 2;          // 0..7  -> rows 4*tm..+3 (batches)
  const int tn = li & 3;           // 0..3  -> cols 8*tn..+7 (= gate tn)

  // epilogue mapping: thread owns (unit uu, batch bl)
  const int uu  = tid >> 5;        // 0..7
  const int bl  = tid & 31;        // 0..31
  const int b_g = b0 + bl;
  const int u_g = ug * 8 + uu;
  float c_reg = 0.f;

  // init h_{-1} slot (layout [u][b])
  hseq[(size_t)u_g * BATCH + b_g] = 0.f;

  // xw addressing for this thread's tile (phase A, warp 0 only)
  constexpr size_t XB = (LAYER == 1) ? (size_t)TSTEPS * 4 * UN1 : (size_t)4 * UN2;
  constexpr size_t XT = (LAYER == 1) ? (size_t)4 * UN1 : (size_t)BATCH * 4 * UN2;
  const size_t xbase = (size_t)(b0 + 4 * tm) * XB + (size_t)tn * UNITS + ug * 8;

  for (int t = 0; t < TSTEPS; t++) {
    // ---- per-bg grid barrier: step t-1 h visible ----
    __syncthreads();
    if (tid == 0) {
      __threadfence();
      atomicAdd(bar, 1u);
      const unsigned tgt = (unsigned)(t + 1) * UG;
      while (*(volatile unsigned*)bar < tgt) { }
      __threadfence();
    }
    __syncthreads();

    // ---- init acc; warp 0 folds in xw (issue LDGs early to hide latency) ----
    float acc[4][8];
    if (q == 0) {
      const float* xp = xw + xbase + (size_t)t * XT;
#pragma unroll
      for (int r = 0; r < 4; r++) {
        float4 lo = *(const float4*)(xp + (size_t)r * XB);
        float4 hi = *(const float4*)(xp + (size_t)r * XB + 4);
        acc[r][0] = lo.x; acc[r][1] = lo.y; acc[r][2] = lo.z; acc[r][3] = lo.w;
        acc[r][4] = hi.x; acc[r][5] = hi.y; acc[r][6] = hi.z; acc[r][7] = hi.w;
      }
    } else {
#pragma unroll
      for (int r = 0; r < 4; r++)
#pragma unroll
        for (int c = 0; c < 8; c++) acc[r][c] = 0.f;
    }

    // ---- stage h_prev [k][b] slice into smem (coalesced, conflict-free) ----
    const float* hp = hseq + (size_t)t * UNITS * BATCH + b0;
    for (int i = tid; i < UNITS * 32; i += 256) {
      int k = i >> 5, bb = i & 31;
      sH[k * SHS + bb] = hp[(size_t)k * BATCH + bb];
    }
    __syncthreads();

    // ---- k-slice GEMM: 4x8 outer products ----
#pragma unroll 8
    for (int kk = 0; kk < KQ; kk++) {
      int k = q * KQ + kk;
      float4 a  = *(const float4*)(sH + k * SHS + 4 * tm);
      float4 u0 = *(const float4*)(sU + k * 32 + 8 * tn);
      float4 u1 = *(const float4*)(sU + k * 32 + 8 * tn + 4);
      acc[0][0] += a.x * u0.x; acc[0][1] += a.x * u0.y; acc[0][2] += a.x * u0.z; acc[0][3] += a.x * u0.w;
      acc[0][4] += a.x * u1.x; acc[0][5] += a.x * u1.y; acc[0][6] += a.x * u1.z; acc[0][7] += a.x * u1.w;
      acc[1][0] += a.y * u0.x; acc[1][1] += a.y * u0.y; acc[1][2] += a.y * u0.z; acc[1][3] += a.y * u0.w;
      acc[1][4] += a.y * u1.x; acc[1][5] += a.y * u1.y; acc[1][6] += a.y * u1.z; acc[1][7] += a.y * u1.w;
      acc[2][0] += a.z * u0.x; acc[2][1] += a.z * u0.y; acc[2][2] += a.z * u0.z; acc[2][3] += a.z * u0.w;
      acc[2][4] += a.z * u1.x; acc[2][5] += a.z * u1.y; acc[2][6] += a.z * u1.z; acc[2][7] += a.z * u1.w;
      acc[3][0] += a.w * u0.x; acc[3][1] += a.w * u0.y; acc[3][2] += a.w * u0.z; acc[3][3] += a.w * u0.w;
      acc[3][4] += a.w * u1.x; acc[3][5] += a.w * u1.y; acc[3][6] += a.w * u1.z; acc[3][7] += a.w * u1.w;
    }

    // ---- store partials ----
#pragma unroll
    for (int r = 0; r < 4; r++) {
      float* zp = sZp + (q * 32 + 4 * tm + r) * 33 + 8 * tn;
#pragma unroll
      for (int v = 0; v < 8; v++) zp[v] = acc[r][v];
    }
    __syncthreads();

    // ---- reduce 8 partials + gates + state update ----
    float z[4];
#pragma unroll
    for (int g = 0; g < 4; g++) {
      float s = 0.f;
#pragma unroll
      for (int q2 = 0; q2 < 8; q2++) s += sZp[(q2 * 32 + bl) * 33 + g * 8 + uu];
      z[g] = s;
    }
    float ig = 1.f / (1.f + __expf(-z[0]));
    float fg = 1.f / (1.f + __expf(-z[1]));
    float gg = fmaxf(z[2], 0.f);
    float og = 1.f / (1.f + __expf(-z[3]));
    c_reg = fg * c_reg + ig * gg;
    float h = og * fmaxf(c_reg, 0.f);
    hseq[(size_t)(t + 1) * UNITS * BATCH + (size_t)u_g * BATCH + b_g] = h;  // coalesced
    if (LAYER == 2 && t == TSTEPS - 1)
      out_last[b_g * UN2 + u_g] = h;
  }

  // ---- exit: last CTA of this bg resets its counters for next graph replay ----
  __syncthreads();
  if (tid == 0) {
    __threadfence();
    if (atomicAdd(exitc, 1u) + 1u == (unsigned)UG) {
      *bar = 0u;
      *exitc = 0u;
    }
  }
}

// ---------------- launch --------------------------------------------------------
extern "C" void kernel_launch(void* const* d_in, const int* in_sizes, int n_in,
                              void* d_out, int out_size) {
  const float* x   = (const float*)d_in[0];  // [128][512][64]
  const float* W1  = (const float*)d_in[1];  // [64][1024]
  const float* U1m = (const float*)d_in[2];  // [256][1024]
  const float* b1  = (const float*)d_in[3];  // [1024]
  const float* W2  = (const float*)d_in[4];  // [256][512]
  const float* U2m = (const float*)d_in[5];  // [128][512]
  const float* b2  = (const float*)d_in[6];  // [512]
  float* out = (float*)d_out;                // [128][128]

  constexpr int SMEM1 = (UN1 * 32 + UN1 * 36 + 8 * 32 * 33) * 4;  // 103424 B
  constexpr int SMEM2 = (UN2 * 32 + UN2 * 36 + 8 * 32 * 33) * 4;  //  68608 B
  cudaFuncSetAttribute(lstm_rec_k<1>, cudaFuncAttributeMaxDynamicSharedMemorySize, SMEM1);
  cudaFuncSetAttribute(lstm_rec_k<2>, cudaFuncAttributeMaxDynamicSharedMemorySize, SMEM2);

  // K1: XW1[b][t][1024] = x @ W1 + b1   (m = (b,t), t-minor)
  gemm_bias<1><<<dim3(1024 / 64, (BATCH * TSTEPS) / 64), 256>>>(
      x, W1, b1, BATCH * TSTEPS, 4 * UN1, FEAT);

  // K2: layer-1 recurrence (persistent, 128 CTAs, per-bg barriers)
  lstm_rec_k<1><<<128, 256, SMEM1>>>(U1m, nullptr);

  // K3: XW2[t][b][512] = h1 @ W2 + b2   (m = (t,b), b-minor; A from [t][u][b])
  gemm_bias<2><<<dim3(512 / 64, (BATCH * TSTEPS) / 64), 256>>>(
      nullptr, W2, b2, BATCH * TSTEPS, 4 * UN2, UN1);

  // K4: layer-2 recurrence (persistent, 64 CTAs) -> writes final h into d_out
  lstm_rec_k<2><<<64, 256, SMEM2>>>(U2m, out);
}

// round 4
// speedup vs baseline: 1.3633x; 1.0548x over previous
#include <cuda_runtime.h>

#define BATCH  128
#define TSTEPS 512
#define FEAT   64
#define UN1    256
#define UN2    128

// packed fp32x2 FMA: two independent fp32 FMAs per instruction (Blackwell)
#define FMA2(acc, a, b) \
  asm("fma.rn.f32x2 %0, %1, %2, %0;" : "+l"(acc) : "l"(a), "l"(b))
#define SPLAT2(dst, x) \
  asm("mov.b64 %0, {%1, %1};" : "=l"(dst) : "r"(__float_as_uint(x)))

// ---------------- scratch (static device globals) ------------------------------
__device__ float g_xw1[(size_t)BATCH * TSTEPS * 4 * UN1];      // [b][t][1024] = x@W1 + b1
__device__ float g_hseq1[(size_t)(TSTEPS + 1) * UN1 * BATCH];  // [t][u][b], slot0 = h_{-1}=0
__device__ float g_xw2[(size_t)TSTEPS * BATCH * 4 * UN2];      // [t][b][512] = h1@W2 + b2
__device__ float g_hseq2[(size_t)(TSTEPS + 1) * UN2 * BATCH];  // [t][u][b]
__device__ unsigned g_bar1[4], g_exit1[4], g_bar2[4], g_exit2[4];  // per batch-group

// ---------------- feed-forward GEMM: C[M,N] = A[M,K] @ W[K,N] + bias[N] --------
// 64x64 tile, 256 threads, 4x4 per-thread register tile, f32x2 accumulation.
template <int PHASE>
__global__ void __launch_bounds__(256)
gemm_bias(const float* __restrict__ Ain, const float* __restrict__ W,
          const float* __restrict__ bias, int M, int N, int K) {
  float* C = (PHASE == 1) ? g_xw1 : g_xw2;

  __shared__ float sA[64][68];  // [k][m]
  __shared__ float sW[64][68];  // [k][n]

  const int n0 = blockIdx.x * 64;
  const int m0 = blockIdx.y * 64;
  const int tid = threadIdx.x;
  const int ty = tid >> 4;
  const int tx = tid & 15;

  unsigned long long acc[4][2];  // 4 rows x 2 col-pairs (4 cols)
#pragma unroll
  for (int r = 0; r < 4; r++) { acc[r][0] = 0ull; acc[r][1] = 0ull; }

  for (int kt = 0; kt < K; kt += 64) {
    if (PHASE == 1) {
      for (int i = tid; i < 64 * 64; i += 256) {
        int r = i >> 6, c = i & 63;
        sA[c][r] = Ain[(size_t)(m0 + r) * K + kt + c];
      }
    } else {
      // A = h1 in [t][u][b] layout; m = t*128 + b (tile = one t, 64 b's)
      int t0 = m0 >> 7, bb = m0 & 127;
      const float* Ab = g_hseq1 + (size_t)(1 + t0) * UN1 * BATCH + bb;
      for (int i = tid; i < 64 * 64; i += 256) {
        int r = i & 63, c = i >> 6;
        sA[c][r] = Ab[(size_t)(kt + c) * BATCH + r];
      }
    }
    for (int i = tid; i < 64 * 64; i += 256) {
      int r = i >> 6, c = i & 63;
      sW[r][c] = W[(size_t)(kt + r) * N + n0 + c];
    }
    __syncthreads();
#pragma unroll 8
    for (int k = 0; k < 64; k++) {
      float4 a = *(const float4*)&sA[k][ty * 4];
      ulonglong2 w2 = *(const ulonglong2*)&sW[k][tx * 4];
      unsigned long long s0, s1, s2, s3;
      SPLAT2(s0, a.x); SPLAT2(s1, a.y); SPLAT2(s2, a.z); SPLAT2(s3, a.w);
      FMA2(acc[0][0], s0, w2.x); FMA2(acc[0][1], s0, w2.y);
      FMA2(acc[1][0], s1, w2.x); FMA2(acc[1][1], s1, w2.y);
      FMA2(acc[2][0], s2, w2.x); FMA2(acc[2][1], s2, w2.y);
      FMA2(acc[3][0], s3, w2.x); FMA2(acc[3][1], s3, w2.y);
    }
    __syncthreads();
  }

  float4 bv = *(const float4*)&bias[n0 + tx * 4];
#pragma unroll
  for (int i = 0; i < 4; i++) {
    float4 o;
    o.x = __uint_as_float((unsigned)(acc[i][0] & 0xffffffffu)) + bv.x;
    o.y = __uint_as_float((unsigned)(acc[i][0] >> 32)) + bv.y;
    o.z = __uint_as_float((unsigned)(acc[i][1] & 0xffffffffu)) + bv.z;
    o.w = __uint_as_float((unsigned)(acc[i][1] >> 32)) + bv.w;
    *(float4*)&C[(size_t)(m0 + ty * 4 + i) * N + n0 + tx * 4] = o;
  }
}

// ---------------- persistent recurrent layer -----------------------------------
// LAYER 1: UNITS=256, 128 CTAs = 4 bg x 32 ug.  LAYER 2: UNITS=128, 64 = 4 x 16.
// CTA computes z tile [32 batches x 32 cols] (cols = 4 gates x 8 units).
// 8 warps; warp q handles k-slice [q*KQ,(q+1)*KQ) with 4x8 tiles (f32x2 cols).
template <int LAYER>
__global__ void __launch_bounds__(256)
lstm_rec_k(const float* __restrict__ Umat, float* __restrict__ out_last) {
  constexpr int UNITS = (LAYER == 1) ? UN1 : UN2;
  constexpr int UG    = UNITS / 8;     // CTAs per batch-group
  constexpr int KQ    = UNITS / 8;     // k per warp-slice
  constexpr int C4U   = 4 * UNITS;
  constexpr int SHS   = 36;            // sH row stride (floats)
  constexpr int ZPS   = 34;            // sZp row stride (floats, 8B-aligned)

  const float* xw = (LAYER == 1) ? g_xw1 : g_xw2;
  float* hseq     = (LAYER == 1) ? g_hseq1 : g_hseq2;
  unsigned* barA  = (LAYER == 1) ? g_bar1 : g_bar2;
  unsigned* exitA = (LAYER == 1) ? g_exit1 : g_exit2;

  extern __shared__ float smem[];
  float* sU  = smem;                   // [UNITS][32]
  float* sH  = sU + UNITS * 32;        // [UNITS][SHS]  ([k][b])
  float* sZp = sH + UNITS * SHS;       // [8*32][ZPS] partial z

  const int tid = threadIdx.x;
  const int bg  = blockIdx.x / UG;
  const int ug  = blockIdx.x % UG;
  const int b0  = bg * 32;
  unsigned* bar   = &barA[bg];
  unsigned* exitc = &exitA[bg];

  // U slice: 32 cols = 4 gates x 8 units, [k][c]
  for (int i = tid; i < UNITS * 32; i += 256) {
    int k = i >> 5, cc = i & 31;
    sU[k * 32 + cc] = Umat[(size_t)k * C4U + (cc >> 3) * UNITS + ug * 8 + (cc & 7)];
  }

  const int q  = tid >> 5;
  const int li = tid & 31;
  const int tm = li >> 2;              // 4 rows: 4*tm..+3
  const int tn = li & 3;               // 8 cols: gate tn, units ug*8..+7

  const int uu  = tid >> 5;
  const int bl  = tid & 31;
  const int b_g = b0 + bl;
  const int u_g = ug * 8 + uu;
  float c_reg = 0.f;

  hseq[(size_t)u_g * BATCH + b_g] = 0.f;   // h_{-1}

  constexpr size_t XB = (LAYER == 1) ? (size_t)TSTEPS * 4 * UN1 : (size_t)4 * UN2;
  constexpr size_t XT = (LAYER == 1) ? (size_t)4 * UN1 : (size_t)BATCH * 4 * UN2;
  const size_t xbase = (size_t)(b0 + 4 * tm) * XB + (size_t)tn * UNITS + ug * 8;

  for (int t = 0; t < TSTEPS; t++) {
    // ---- prefetch xw tile (h-independent) BEFORE the grid barrier ----
    ulonglong2 xv[4][1];
    ulonglong2 xw0[4], xw1[4];
    if (q == 0) {
      const float* xp = xw + xbase + (size_t)t * XT;
#pragma unroll
      for (int r = 0; r < 4; r++) {
        xw0[r] = *(const ulonglong2*)(xp + (size_t)r * XB);
        xw1[r] = *(const ulonglong2*)(xp + (size_t)r * XB + 4);
      }
    }
    (void)xv;

    // ---- per-bg grid barrier: step t-1 h visible ----
    __syncthreads();
    if (tid == 0) {
      __threadfence();
      atomicAdd(bar, 1u);
      const unsigned tgt = (unsigned)(t + 1) * UG;
      while (*(volatile unsigned*)bar < tgt) { }
      __threadfence();
    }
    __syncthreads();

    // ---- stage h_prev [k][b] into smem (coalesced, conflict-free) ----
    {
      const float* hp = hseq + (size_t)t * UNITS * BATCH + b0;
      for (int i = tid; i < UNITS * 8; i += 256) {     // float4 granules
        int k = i >> 3, b4 = (i & 7) << 2;
        *(float4*)(sH + k * SHS + b4) = *(const float4*)(hp + (size_t)k * BATCH + b4);
      }
    }

    // ---- init acc (warp 0 folds in xw) ----
    unsigned long long acc[4][4];
    if (q == 0) {
#pragma unroll
      for (int r = 0; r < 4; r++) {
        acc[r][0] = xw0[r].x; acc[r][1] = xw0[r].y;
        acc[r][2] = xw1[r].x; acc[r][3] = xw1[r].y;
      }
    } else {
#pragma unroll
      for (int r = 0; r < 4; r++)
#pragma unroll
        for (int c = 0; c < 4; c++) acc[r][c] = 0ull;
    }
    __syncthreads();

    // ---- k-slice GEMM: 4x8 outer products, f32x2 ----
#pragma unroll 8
    for (int kk = 0; kk < KQ; kk++) {
      int k = q * KQ + kk;
      float4 a = *(const float4*)(sH + k * SHS + 4 * tm);
      ulonglong2 uA = *(const ulonglong2*)(sU + k * 32 + 8 * tn);
      ulonglong2 uB = *(const ulonglong2*)(sU + k * 32 + 8 * tn + 4);
      unsigned long long s0, s1, s2, s3;
      SPLAT2(s0, a.x); SPLAT2(s1, a.y); SPLAT2(s2, a.z); SPLAT2(s3, a.w);
      FMA2(acc[0][0], s0, uA.x); FMA2(acc[0][1], s0, uA.y);
      FMA2(acc[0][2], s0, uB.x); FMA2(acc[0][3], s0, uB.y);
      FMA2(acc[1][0], s1, uA.x); FMA2(acc[1][1], s1, uA.y);
      FMA2(acc[1][2], s1, uB.x); FMA2(acc[1][3], s1, uB.y);
      FMA2(acc[2][0], s2, uA.x); FMA2(acc[2][1], s2, uA.y);
      FMA2(acc[2][2], s2, uB.x); FMA2(acc[2][3], s2, uB.y);
      FMA2(acc[3][0], s3, uA.x); FMA2(acc[3][1], s3, uA.y);
      FMA2(acc[3][2], s3, uB.x); FMA2(acc[3][3], s3, uB.y);
    }

    // ---- store partials (float2 per pair; row stride 34 floats) ----
#pragma unroll
    for (int r = 0; r < 4; r++) {
      float* zp = sZp + (q * 32 + 4 * tm + r) * ZPS + 8 * tn;
#pragma unroll
      for (int p = 0; p < 4; p++) {
        float2 v;
        v.x = __uint_as_float((unsigned)(acc[r][p] & 0xffffffffu));
        v.y = __uint_as_float((unsigned)(acc[r][p] >> 32));
        *(float2*)(zp + 2 * p) = v;
      }
    }
    __syncthreads();

    // ---- reduce 8 partials + gates + state update ----
    float z[4];
#pragma unroll
    for (int g = 0; g < 4; g++) {
      float s = 0.f;
#pragma unroll
      for (int q2 = 0; q2 < 8; q2++) s += sZp[(q2 * 32 + bl) * ZPS + g * 8 + uu];
      z[g] = s;
    }
    float ig = 1.f / (1.f + __expf(-z[0]));
    float fg = 1.f / (1.f + __expf(-z[1]));
    float gg = fmaxf(z[2], 0.f);
    float og = 1.f / (1.f + __expf(-z[3]));
    c_reg = fg * c_reg + ig * gg;
    float h = og * fmaxf(c_reg, 0.f);
    hseq[(size_t)(t + 1) * UNITS * BATCH + (size_t)u_g * BATCH + b_g] = h;
    if (LAYER == 2 && t == TSTEPS - 1)
      out_last[b_g * UN2 + u_g] = h;
  }

  // ---- exit: last CTA of this bg resets counters for next graph replay ----
  __syncthreads();
  if (tid == 0) {
    __threadfence();
    if (atomicAdd(exitc, 1u) + 1u == (unsigned)UG) {
      *bar = 0u;
      *exitc = 0u;
    }
  }
}

// ---------------- launch --------------------------------------------------------
extern "C" void kernel_launch(void* const* d_in, const int* in_sizes, int n_in,
                              void* d_out, int out_size) {
  const float* x   = (const float*)d_in[0];  // [128][512][64]
  const float* W1  = (const float*)d_in[1];  // [64][1024]
  const float* U1m = (const float*)d_in[2];  // [256][1024]
  const float* b1  = (const float*)d_in[3];  // [1024]
  const float* W2  = (const float*)d_in[4];  // [256][512]
  const float* U2m = (const float*)d_in[5];  // [128][512]
  const float* b2  = (const float*)d_in[6];  // [512]
  float* out = (float*)d_out;                // [128][128]

  constexpr int SMEM1 = (UN1 * 32 + UN1 * 36 + 8 * 32 * 34) * 4;  // 104448 B
  constexpr int SMEM2 = (UN2 * 32 + UN2 * 36 + 8 * 32 * 34) * 4;  //  69632 B
  cudaFuncSetAttribute(lstm_rec_k<1>, cudaFuncAttributeMaxDynamicSharedMemorySize, SMEM1);
  cudaFuncSetAttribute(lstm_rec_k<2>, cudaFuncAttributeMaxDynamicSharedMemorySize, SMEM2);

  // K1: XW1[b][t][1024] = x @ W1 + b1
  gemm_bias<1><<<dim3(1024 / 64, (BATCH * TSTEPS) / 64), 256>>>(
      x, W1, b1, BATCH * TSTEPS, 4 * UN1, FEAT);

  // K2: layer-1 recurrence (persistent, 128 CTAs, per-bg barriers)
  lstm_rec_k<1><<<128, 256, SMEM1>>>(U1m, nullptr);

  // K3: XW2[t][b][512] = h1 @ W2 + b2
  gemm_bias<2><<<dim3(512 / 64, (BATCH * TSTEPS) / 64), 256>>>(
      nullptr, W2, b2, BATCH * TSTEPS, 4 * UN2, UN1);

  // K4: layer-2 recurrence (persistent, 64 CTAs) -> writes final h into d_out
  lstm_rec_k<2><<<64, 256, SMEM2>>>(U2m, out);
}

// round 5
// speedup vs baseline: 1.8571x; 1.3622x over previous
#include <cuda_runtime.h>

#define BATCH  128
#define TSTEPS 512
#define FEAT   64
#define UN1    256
#define UN2    128

// packed fp32x2 FMA (Blackwell): two fp32 FMAs per instruction
#define FMA2(acc, a, b) \
  asm("fma.rn.f32x2 %0, %1, %2, %0;" : "+l"(acc) : "l"(a), "l"(b))
#define SPLAT2(dst, x) \
  asm("mov.b64 %0, {%1, %1};" : "=l"(dst) : "r"(__float_as_uint(x)))

// ---------------- scratch ------------------------------------------------------
__device__ float g_hseq1[(size_t)(TSTEPS + 1) * UN1 * BATCH];  // [t][u][b], slot0 = 0
__device__ float g_hseq2[(size_t)(TSTEPS + 1) * UN2 * BATCH];  // [t][u][b], slot0 = 0
__device__ unsigned g_bar[4], g_exit[4];                       // per batch-group

// ---------------- fused persistent 2-layer LSTM --------------------------------
// 128 CTAs = 4 bg (32 batches) x 32 ug.
// Per step t (t = 0..512):
//   L1 (t<512): z1 tile [32 b x 32 cols] (4 gates x 8 units), K = 64(x@W1)+256(h1@U1)
//   L2 (t>=1): z2 tile [32 b x 16 cols] (4 gates x 4 units), K = 256(h1@W2)+128(h2@U2)
//   computes h2_{t-1}; L2's W2-part reuses the sH stage of h1_{t-1}.
// One bg-scoped grid barrier per step orders h1_t and h2_{t-1} stores.
__global__ void __launch_bounds__(256)
lstm_fused(const float* __restrict__ x,
           const float* __restrict__ W1, const float* __restrict__ U1m,
           const float* __restrict__ b1,
           const float* __restrict__ W2, const float* __restrict__ U2m,
           const float* __restrict__ b2,
           float* __restrict__ out_last) {
  constexpr int SHS  = 36;   // sH / sH2e / sX row stride
  constexpr int ZPS  = 34;   // sZp1 row stride
  constexpr int ZP2S = 20;   // sZp2 row stride (float4-aligned)

  extern __shared__ float smem[];
  float* sU1  = smem;                   // [256][32]  U1 slice
  float* sW1x = sU1 + 256 * 32;         // [64][32]   W1 slice
  float* sUW2 = sW1x + 64 * 32;         // [384][16]  W2 (k<256) + U2 (k>=256) slice
  float* sH   = sUW2 + 384 * 16;        // [256][SHS] h1_{t-1} [k][b]
  float* sH2e = sH + 256 * SHS;         // [128][SHS] h2_{t-2} [k][b]
  float* sX   = sH2e + 128 * SHS;       // [64][SHS]  x_t [f][b]
  float* sZp1 = sX + 64 * SHS;          // [8*32][ZPS]
  float* sZp2 = sZp1 + 256 * ZPS;       // [8*32][ZP2S]

  const int tid = threadIdx.x;
  const int bg  = blockIdx.x >> 5;          // 0..3
  const int ug  = blockIdx.x & 31;          // 0..31
  const int b0  = bg * 32;
  unsigned* bar   = &g_bar[bg];
  unsigned* exitc = &g_exit[bg];

  // ---- load weight slices into smem (once) ----
  for (int i = tid; i < 256 * 32; i += 256) {           // U1 [k][32 cols]
    int k = i >> 5, cc = i & 31;
    sU1[i] = U1m[(size_t)k * 1024 + (cc >> 3) * 256 + ug * 8 + (cc & 7)];
  }
  for (int i = tid; i < 64 * 32; i += 256) {            // W1 [k][32 cols]
    int k = i >> 5, cc = i & 31;
    sW1x[i] = W1[(size_t)k * 1024 + (cc >> 3) * 256 + ug * 8 + (cc & 7)];
  }
  for (int i = tid; i < 384 * 16; i += 256) {           // W2;U2 [k][16 cols]
    int k = i >> 4, c = i & 15;
    int col = (c >> 2) * 128 + ug * 4 + (c & 3);
    sUW2[i] = (k < 256) ? W2[(size_t)k * 512 + col]
                        : U2m[(size_t)(k - 256) * 512 + col];
  }

  // ---- thread mappings ----
  const int q  = tid >> 5;           // warp = k-slice
  const int li = tid & 31;
  const int tm = li >> 2;            // rows 4*tm..+3
  const int tn = li & 3;             // gate index

  // L1 epilogue: (uu 0..7, bl 0..31)
  const int uu  = tid >> 5;
  const int bl  = tid & 31;
  const int b_g = b0 + bl;
  const int u_g = ug * 8 + uu;       // L1 unit
  // L2 epilogue (tid<128): uu2 0..3
  const int uu2  = (tid >> 5) & 3;
  const int u_g2 = ug * 4 + uu2;     // L2 unit

  float c1 = 0.f, c2 = 0.f;

  // biases into registers
  float b1g[4], b2g[4];
#pragma unroll
  for (int g = 0; g < 4; g++) b1g[g] = b1[g * 256 + u_g];
  if (tid < 128) {
#pragma unroll
    for (int g = 0; g < 4; g++) b2g[g] = b2[g * 128 + u_g2];
  }

  // init h_{-1} slots
  g_hseq1[(size_t)u_g * BATCH + b_g] = 0.f;
  if (tid < 128) g_hseq2[(size_t)u_g2 * BATCH + b_g] = 0.f;

  for (int t = 0; t <= TSTEPS; t++) {
    // ---- bg grid barrier: h1_{t-1} and h2_{t-2} stores visible ----
    __syncthreads();
    if (tid == 0) {
      __threadfence();
      atomicAdd(bar, 1u);
      const unsigned tgt = (unsigned)(t + 1) * 32u;
      unsigned v;
      do {
        asm volatile("ld.acquire.gpu.global.u32 %0, [%1];" : "=r"(v) : "l"(bar));
      } while (v < tgt);
    }
    __syncthreads();

    // ---- stage sH = h1_{t-1} [256][32b] ----
    {
      const float* hp = g_hseq1 + (size_t)t * UN1 * BATCH + b0;
      for (int i = tid; i < 256 * 8; i += 256) {
        int k = i >> 3, b4 = (i & 7) << 2;
        *(float4*)(sH + k * SHS + b4) = *(const float4*)(hp + (size_t)k * BATCH + b4);
      }
    }
    // ---- stage sH2e = h2_{t-2} [128][32b] ----
    if (t >= 1) {
      const float* hp = g_hseq2 + (size_t)(t - 1) * UN2 * BATCH + b0;
      for (int i = tid; i < 128 * 8; i += 256) {
        int k = i >> 3, b4 = (i & 7) << 2;
        *(float4*)(sH2e + k * SHS + b4) = *(const float4*)(hp + (size_t)k * BATCH + b4);
      }
    }
    // ---- stage sX = x_t [64 f][32 b] (transposed) ----
    if (t < TSTEPS) {
      for (int i = tid; i < 512; i += 256) {
        int bb = i >> 4, f4 = (i & 15) << 2;
        float4 v = *(const float4*)(x + (size_t)(b0 + bb) * TSTEPS * FEAT
                                      + (size_t)t * FEAT + f4);
        sX[(f4 + 0) * SHS + bb] = v.x;
        sX[(f4 + 1) * SHS + bb] = v.y;
        sX[(f4 + 2) * SHS + bb] = v.z;
        sX[(f4 + 3) * SHS + bb] = v.w;
      }
    }
    __syncthreads();

    // ================= L1 compute: 4x8 tile, K = 64 + 256 =================
    if (t < TSTEPS) {
      unsigned long long acc[4][4];
#pragma unroll
      for (int r = 0; r < 4; r++)
#pragma unroll
        for (int c = 0; c < 4; c++) acc[r][c] = 0ull;

      // x-part: k slice [8q, 8q+8)
#pragma unroll
      for (int kk = 0; kk < 8; kk++) {
        int k = q * 8 + kk;
        float4 a = *(const float4*)(sX + k * SHS + 4 * tm);
        ulonglong2 uA = *(const ulonglong2*)(sW1x + k * 32 + 8 * tn);
        ulonglong2 uB = *(const ulonglong2*)(sW1x + k * 32 + 8 * tn + 4);
        unsigned long long s0, s1, s2, s3;
        SPLAT2(s0, a.x); SPLAT2(s1, a.y); SPLAT2(s2, a.z); SPLAT2(s3, a.w);
        FMA2(acc[0][0], s0, uA.x); FMA2(acc[0][1], s0, uA.y);
        FMA2(acc[0][2], s0, uB.x); FMA2(acc[0][3], s0, uB.y);
        FMA2(acc[1][0], s1, uA.x); FMA2(acc[1][1], s1, uA.y);
        FMA2(acc[1][2], s1, uB.x); FMA2(acc[1][3], s1, uB.y);
        FMA2(acc[2][0], s2, uA.x); FMA2(acc[2][1], s2, uA.y);
        FMA2(acc[2][2], s2, uB.x); FMA2(acc[2][3], s2, uB.y);
        FMA2(acc[3][0], s3, uA.x); FMA2(acc[3][1], s3, uA.y);
        FMA2(acc[3][2], s3, uB.x); FMA2(acc[3][3], s3, uB.y);
      }
      // h-part: k slice [32q, 32q+32)
#pragma unroll 8
      for (int kk = 0; kk < 32; kk++) {
        int k = q * 32 + kk;
        float4 a = *(const float4*)(sH + k * SHS + 4 * tm);
        ulonglong2 uA = *(const ulonglong2*)(sU1 + k * 32 + 8 * tn);
        ulonglong2 uB = *(const ulonglong2*)(sU1 + k * 32 + 8 * tn + 4);
        unsigned long long s0, s1, s2, s3;
        SPLAT2(s0, a.x); SPLAT2(s1, a.y); SPLAT2(s2, a.z); SPLAT2(s3, a.w);
        FMA2(acc[0][0], s0, uA.x); FMA2(acc[0][1], s0, uA.y);
        FMA2(acc[0][2], s0, uB.x); FMA2(acc[0][3], s0, uB.y);
        FMA2(acc[1][0], s1, uA.x); FMA2(acc[1][1], s1, uA.y);
        FMA2(acc[1][2], s1, uB.x); FMA2(acc[1][3], s1, uB.y);
        FMA2(acc[2][0], s2, uA.x); FMA2(acc[2][1], s2, uA.y);
        FMA2(acc[2][2], s2, uB.x); FMA2(acc[2][3], s2, uB.y);
        FMA2(acc[3][0], s3, uA.x); FMA2(acc[3][1], s3, uA.y);
        FMA2(acc[3][2], s3, uB.x); FMA2(acc[3][3], s3, uB.y);
      }
      // store partials
#pragma unroll
      for (int r = 0; r < 4; r++) {
        float* zp = sZp1 + (q * 32 + 4 * tm + r) * ZPS + 8 * tn;
#pragma unroll
        for (int p = 0; p < 4; p++) {
          float2 v;
          v.x = __uint_as_float((unsigned)(acc[r][p] & 0xffffffffu));
          v.y = __uint_as_float((unsigned)(acc[r][p] >> 32));
          *(float2*)(zp + 2 * p) = v;
        }
      }
    }

    // ================= L2 compute: 4x4 tile, K = 256 + 128 =================
    if (t >= 1) {
      unsigned long long acc2[4][2];
#pragma unroll
      for (int r = 0; r < 4; r++) { acc2[r][0] = 0ull; acc2[r][1] = 0ull; }

      // W2-part over h1_{t-1} (reuses sH): k slice [32q, 32q+32)
#pragma unroll 8
      for (int kk = 0; kk < 32; kk++) {
        int k = q * 32 + kk;
        float4 a = *(const float4*)(sH + k * SHS + 4 * tm);
        ulonglong2 u2 = *(const ulonglong2*)(sUW2 + k * 16 + 4 * tn);
        unsigned long long s0, s1, s2, s3;
        SPLAT2(s0, a.x); SPLAT2(s1, a.y); SPLAT2(s2, a.z); SPLAT2(s3, a.w);
        FMA2(acc2[0][0], s0, u2.x); FMA2(acc2[0][1], s0, u2.y);
        FMA2(acc2[1][0], s1, u2.x); FMA2(acc2[1][1], s1, u2.y);
        FMA2(acc2[2][0], s2, u2.x); FMA2(acc2[2][1], s2, u2.y);
        FMA2(acc2[3][0], s3, u2.x); FMA2(acc2[3][1], s3, u2.y);
      }
      // U2-part over h2_{t-2}: k slice [16q, 16q+16)
#pragma unroll 8
      for (int kk = 0; kk < 16; kk++) {
        int k = q * 16 + kk;
        float4 a = *(const float4*)(sH2e + k * SHS + 4 * tm);
        ulonglong2 u2 = *(const ulonglong2*)(sUW2 + (256 + k) * 16 + 4 * tn);
        unsigned long long s0, s1, s2, s3;
        SPLAT2(s0, a.x); SPLAT2(s1, a.y); SPLAT2(s2, a.z); SPLAT2(s3, a.w);
        FMA2(acc2[0][0], s0, u2.x); FMA2(acc2[0][1], s0, u2.y);
        FMA2(acc2[1][0], s1, u2.x); FMA2(acc2[1][1], s1, u2.y);
        FMA2(acc2[2][0], s2, u2.x); FMA2(acc2[2][1], s2, u2.y);
        FMA2(acc2[3][0], s3, u2.x); FMA2(acc2[3][1], s3, u2.y);
      }
      // store partials (float4 per row: cols 4tn..+3)
#pragma unroll
      for (int r = 0; r < 4; r++) {
        float4 v;
        v.x = __uint_as_float((unsigned)(acc2[r][0] & 0xffffffffu));
        v.y = __uint_as_float((unsigned)(acc2[r][0] >> 32));
        v.z = __uint_as_float((unsigned)(acc2[r][1] & 0xffffffffu));
        v.w = __uint_as_float((unsigned)(acc2[r][1] >> 32));
        *(float4*)(sZp2 + (q * 32 + 4 * tm + r) * ZP2S + 4 * tn) = v;
      }
    }
    __syncthreads();

    // ---- L1 reduce + state update ----
    if (t < TSTEPS) {
      float z[4];
#pragma unroll
      for (int g = 0; g < 4; g++) {
        float s = b1g[g];
#pragma unroll
        for (int q2 = 0; q2 < 8; q2++) s += sZp1[(q2 * 32 + bl) * ZPS + g * 8 + uu];
        z[g] = s;
      }
      float ig = 1.f / (1.f + __expf(-z[0]));
      float fg = 1.f / (1.f + __expf(-z[1]));
      float gg = fmaxf(z[2], 0.f);
      float og = 1.f / (1.f + __expf(-z[3]));
      c1 = fg * c1 + ig * gg;
      float h = og * fmaxf(c1, 0.f);
      g_hseq1[(size_t)(t + 1) * UN1 * BATCH + (size_t)u_g * BATCH + b_g] = h;
    }

    // ---- L2 reduce + state update (computes h2_{t-1}) ----
    if (t >= 1 && tid < 128) {
      float z[4];
#pragma unroll
      for (int g = 0; g < 4; g++) {
        float s = b2g[g];
#pragma unroll
        for (int q2 = 0; q2 < 8; q2++) s += sZp2[(q2 * 32 + bl) * ZP2S + g * 4 + uu2];
        z[g] = s;
      }
      float ig = 1.f / (1.f + __expf(-z[0]));
      float fg = 1.f / (1.f + __expf(-z[1]));
      float gg = fmaxf(z[2], 0.f);
      float og = 1.f / (1.f + __expf(-z[3]));
      c2 = fg * c2 + ig * gg;
      float h = og * fmaxf(c2, 0.f);
      if (t < TSTEPS)
        g_hseq2[(size_t)t * UN2 * BATCH + (size_t)u_g2 * BATCH + b_g] = h;
      else
        out_last[b_g * UN2 + u_g2] = h;   // h2_{511} -> output
    }
  }

  // ---- exit: last CTA of this bg resets counters for next graph replay ----
  __syncthreads();
  if (tid == 0) {
    __threadfence();
    if (atomicAdd(exitc, 1u) + 1u == 32u) {
      *bar = 0u;
      *exitc = 0u;
    }
  }
}

// ---------------- launch --------------------------------------------------------
extern "C" void kernel_launch(void* const* d_in, const int* in_sizes, int n_in,
                              void* d_out, int out_size) {
  const float* x   = (const float*)d_in[0];  // [128][512][64]
  const float* W1  = (const float*)d_in[1];  // [64][1024]
  const float* U1m = (const float*)d_in[2];  // [256][1024]
  const float* b1  = (const float*)d_in[3];  // [1024]
  const float* W2  = (const float*)d_in[4];  // [256][512]
  const float* U2m = (const float*)d_in[5];  // [128][512]
  const float* b2  = (const float*)d_in[6];  // [512]
  float* out = (float*)d_out;                // [128][128]

  constexpr int SMEM = (256 * 32 + 64 * 32 + 384 * 16 + 256 * 36 + 128 * 36 +
                        64 * 36 + 256 * 34 + 256 * 20) * 4;   // 185344 B
  cudaFuncSetAttribute(lstm_fused, cudaFuncAttributeMaxDynamicSharedMemorySize, SMEM);

  lstm_fused<<<128, 256, SMEM>>>(x, W1, U1m, b1, W2, U2m, b2, out);
}

// round 6
// speedup vs baseline: 2.1913x; 1.1799x over previous
#include <cuda_runtime.h>

#define BATCH  128
#define TSTEPS 512
#define FEAT   64
#define UN1    256
#define UN2    128

// packed fp32x2 FMA (Blackwell): two fp32 FMAs per instruction
#define FMA2(acc, a, b) \
  asm("fma.rn.f32x2 %0, %1, %2, %0;" : "+l"(acc) : "l"(a), "l"(b))
#define SPLAT2(dst, x) \
  asm("mov.b64 %0, {%1, %1};" : "=l"(dst) : "r"(__float_as_uint(x)))

#define CP_ASYNC16(saddr, gaddr) \
  asm volatile("cp.async.cg.shared.global [%0], [%1], 16;" :: "r"(saddr), "l"(gaddr))
#define CP_COMMIT() asm volatile("cp.async.commit_group;")
#define CP_WAIT0()  asm volatile("cp.async.wait_group 0;")

// ---------------- scratch ------------------------------------------------------
__device__ float g_hseq1[(size_t)(TSTEPS + 1) * UN1 * BATCH];  // [t][u][b], slot0 = 0
__device__ float g_hseq2[(size_t)(TSTEPS + 1) * UN2 * BATCH];  // [t][u][b], slot0 = 0
__device__ unsigned g_bar[4], g_exit[4];                       // per batch-group

// ---------------- fused persistent 2-layer LSTM --------------------------------
// 128 CTAs = 4 bg (32 batches) x 32 ug. One release/acquire bg-barrier per step.
// Step t: L1 computes h1_t (t<512); L2 computes h2_{t-1} (t>=1), reusing sH.
__global__ void __launch_bounds__(256)
lstm_fused(const float* __restrict__ x,
           const float* __restrict__ W1, const float* __restrict__ U1m,
           const float* __restrict__ b1,
           const float* __restrict__ W2, const float* __restrict__ U2m,
           const float* __restrict__ b2,
           float* __restrict__ out_last) {
  constexpr int SHS  = 36;   // sH / sH2e / sX row stride
  constexpr int ZPS  = 34;   // sZp1 row stride
  constexpr int ZP2S = 20;   // sZp2 row stride

  extern __shared__ float smem[];
  float* sU1  = smem;                   // [256][32]
  float* sW1x = sU1 + 256 * 32;         // [64][32]
  float* sUW2 = sW1x + 64 * 32;         // [384][16]  W2 | U2
  float* sH   = sUW2 + 384 * 16;        // [256][SHS] h1_{t-1} [k][b]
  float* sH2e = sH + 256 * SHS;         // [128][SHS] h2_{t-2} [k][b]
  float* sX   = sH2e + 128 * SHS;       // [64][SHS]  x_t [f][b]
  float* sZp1 = sX + 64 * SHS;          // [8*32][ZPS]
  float* sZp2 = sZp1 + 256 * ZPS;       // [8*32][ZP2S]

  const int tid = threadIdx.x;
  const int bg  = blockIdx.x >> 5;
  const int ug  = blockIdx.x & 31;
  const int b0  = bg * 32;
  unsigned* bar   = &g_bar[bg];
  unsigned* exitc = &g_exit[bg];

  // ---- weight slices (once) ----
  for (int i = tid; i < 256 * 32; i += 256) {
    int k = i >> 5, cc = i & 31;
    sU1[i] = U1m[(size_t)k * 1024 + (cc >> 3) * 256 + ug * 8 + (cc & 7)];
  }
  for (int i = tid; i < 64 * 32; i += 256) {
    int k = i >> 5, cc = i & 31;
    sW1x[i] = W1[(size_t)k * 1024 + (cc >> 3) * 256 + ug * 8 + (cc & 7)];
  }
  for (int i = tid; i < 384 * 16; i += 256) {
    int k = i >> 4, c = i & 15;
    int col = (c >> 2) * 128 + ug * 4 + (c & 3);
    sUW2[i] = (k < 256) ? W2[(size_t)k * 512 + col]
                        : U2m[(size_t)(k - 256) * 512 + col];
  }

  // ---- thread mappings ----
  const int q  = tid >> 5;
  const int li = tid & 31;
  const int tm = li >> 2;            // rows 4*tm..+3
  const int tn = li & 3;             // gate

  const int uu  = tid >> 5;
  const int bl  = tid & 31;
  const int b_g = b0 + bl;
  const int u_g = ug * 8 + uu;
  const int uu2  = (tid >> 5) & 3;
  const int u_g2 = ug * 4 + uu2;

  float c1 = 0.f, c2 = 0.f;
  float b1g[4], b2g[4];
#pragma unroll
  for (int g = 0; g < 4; g++) b1g[g] = b1[g * 256 + u_g];
  if (tid < 128) {
#pragma unroll
    for (int g = 0; g < 4; g++) b2g[g] = b2[g * 128 + u_g2];
  }

  // smem u32 bases for cp.async
  const unsigned sH_u   = (unsigned)__cvta_generic_to_shared(sH);
  const unsigned sH2e_u = (unsigned)__cvta_generic_to_shared(sH2e);

  // ---- init h_{-1} + first arrive + stage sX(t=0) ----
  g_hseq1[(size_t)u_g * BATCH + b_g] = 0.f;
  if (tid < 128) g_hseq2[(size_t)u_g2 * BATCH + b_g] = 0.f;
  __syncthreads();
  if (tid == 0)
    asm volatile("red.release.gpu.global.add.u32 [%0], %1;" :: "l"(bar), "r"(1u));
  for (int i = tid; i < 512; i += 256) {
    int bb = i >> 4, f4 = (i & 15) << 2;
    float4 v = *(const float4*)(x + (size_t)(b0 + bb) * TSTEPS * FEAT + f4);
    sX[(f4 + 0) * SHS + bb] = v.x;
    sX[(f4 + 1) * SHS + bb] = v.y;
    sX[(f4 + 2) * SHS + bb] = v.z;
    sX[(f4 + 3) * SHS + bb] = v.w;
  }

  for (int t = 0; t <= TSTEPS; t++) {
    // ---- wait: h1_{t-1}, h2_{t-2} sealed ----
    if (tid == 0) {
      const unsigned tgt = (unsigned)(t + 1) * 32u;
      unsigned v;
      do {
        asm volatile("ld.relaxed.gpu.global.u32 %0, [%1];" : "=r"(v) : "l"(bar));
      } while (v < tgt);
      asm volatile("ld.acquire.gpu.global.u32 %0, [%1];" : "=r"(v) : "l"(bar));
    }
    __syncthreads();

    // ---- issue async staging: sH = h1_{t-1}; sH2e = h2_{t-2} ----
    {
      const float* hp = g_hseq1 + (size_t)t * UN1 * BATCH + b0;
#pragma unroll
      for (int j = 0; j < 8; j++) {
        int i = tid + j * 256;
        int k = i >> 3, b4 = (i & 7) << 2;
        CP_ASYNC16(sH_u + (unsigned)(k * SHS + b4) * 4u,
                   hp + (size_t)k * BATCH + b4);
      }
    }
    if (t >= 1) {
      const float* hp = g_hseq2 + (size_t)(t - 1) * UN2 * BATCH + b0;
#pragma unroll
      for (int j = 0; j < 4; j++) {
        int i = tid + j * 256;
        int k = i >> 3, b4 = (i & 7) << 2;
        CP_ASYNC16(sH2e_u + (unsigned)(k * SHS + b4) * 4u,
                   hp + (size_t)k * BATCH + b4);
      }
    }
    CP_COMMIT();

    // ---- L1 x-part while copies fly (sX staged pre-arrive) ----
    unsigned long long acc[4][4];
#pragma unroll
    for (int r = 0; r < 4; r++)
#pragma unroll
      for (int c = 0; c < 4; c++) acc[r][c] = 0ull;
    if (t < TSTEPS) {
#pragma unroll
      for (int kk = 0; kk < 8; kk++) {
        int k = q * 8 + kk;
        float4 a = *(const float4*)(sX + k * SHS + 4 * tm);
        ulonglong2 uA = *(const ulonglong2*)(sW1x + k * 32 + 8 * tn);
        ulonglong2 uB = *(const ulonglong2*)(sW1x + k * 32 + 8 * tn + 4);
        unsigned long long s0, s1, s2, s3;
        SPLAT2(s0, a.x); SPLAT2(s1, a.y); SPLAT2(s2, a.z); SPLAT2(s3, a.w);
        FMA2(acc[0][0], s0, uA.x); FMA2(acc[0][1], s0, uA.y);
        FMA2(acc[0][2], s0, uB.x); FMA2(acc[0][3], s0, uB.y);
        FMA2(acc[1][0], s1, uA.x); FMA2(acc[1][1], s1, uA.y);
        FMA2(acc[1][2], s1, uB.x); FMA2(acc[1][3], s1, uB.y);
        FMA2(acc[2][0], s2, uA.x); FMA2(acc[2][1], s2, uA.y);
        FMA2(acc[2][2], s2, uB.x); FMA2(acc[2][3], s2, uB.y);
        FMA2(acc[3][0], s3, uA.x); FMA2(acc[3][1], s3, uA.y);
        FMA2(acc[3][2], s3, uB.x); FMA2(acc[3][3], s3, uB.y);
      }
    }
    CP_WAIT0();
    __syncthreads();

    // ---- L1 h-part ----
    if (t < TSTEPS) {
#pragma unroll 8
      for (int kk = 0; kk < 32; kk++) {
        int k = q * 32 + kk;
        float4 a = *(const float4*)(sH + k * SHS + 4 * tm);
        ulonglong2 uA = *(const ulonglong2*)(sU1 + k * 32 + 8 * tn);
        ulonglong2 uB = *(const ulonglong2*)(sU1 + k * 32 + 8 * tn + 4);
        unsigned long long s0, s1, s2, s3;
        SPLAT2(s0, a.x); SPLAT2(s1, a.y); SPLAT2(s2, a.z); SPLAT2(s3, a.w);
        FMA2(acc[0][0], s0, uA.x); FMA2(acc[0][1], s0, uA.y);
        FMA2(acc[0][2], s0, uB.x); FMA2(acc[0][3], s0, uB.y);
        FMA2(acc[1][0], s1, uA.x); FMA2(acc[1][1], s1, uA.y);
        FMA2(acc[1][2], s1, uB.x); FMA2(acc[1][3], s1, uB.y);
        FMA2(acc[2][0], s2, uA.x); FMA2(acc[2][1], s2, uA.y);
        FMA2(acc[2][2], s2, uB.x); FMA2(acc[2][3], s2, uB.y);
        FMA2(acc[3][0], s3, uA.x); FMA2(acc[3][1], s3, uA.y);
        FMA2(acc[3][2], s3, uB.x); FMA2(acc[3][3], s3, uB.y);
      }
#pragma unroll
      for (int r = 0; r < 4; r++) {
        float* zp = sZp1 + (q * 32 + 4 * tm + r) * ZPS + 8 * tn;
#pragma unroll
        for (int p = 0; p < 4; p++) {
          float2 v;
          v.x = __uint_as_float((unsigned)(acc[r][p] & 0xffffffffu));
          v.y = __uint_as_float((unsigned)(acc[r][p] >> 32));
          *(float2*)(zp + 2 * p) = v;
        }
      }
    }

    // ---- L2: W2-part over sH + U2-part over sH2e ----
    if (t >= 1) {
      unsigned long long acc2[4][2];
#pragma unroll
      for (int r = 0; r < 4; r++) { acc2[r][0] = 0ull; acc2[r][1] = 0ull; }
#pragma unroll 8
      for (int kk = 0; kk < 32; kk++) {
        int k = q * 32 + kk;
        float4 a = *(const float4*)(sH + k * SHS + 4 * tm);
        ulonglong2 u2 = *(const ulonglong2*)(sUW2 + k * 16 + 4 * tn);
        unsigned long long s0, s1, s2, s3;
        SPLAT2(s0, a.x); SPLAT2(s1, a.y); SPLAT2(s2, a.z); SPLAT2(s3, a.w);
        FMA2(acc2[0][0], s0, u2.x); FMA2(acc2[0][1], s0, u2.y);
        FMA2(acc2[1][0], s1, u2.x); FMA2(acc2[1][1], s1, u2.y);
        FMA2(acc2[2][0], s2, u2.x); FMA2(acc2[2][1], s2, u2.y);
        FMA2(acc2[3][0], s3, u2.x); FMA2(acc2[3][1], s3, u2.y);
      }
#pragma unroll 8
      for (int kk = 0; kk < 16; kk++) {
        int k = q * 16 + kk;
        float4 a = *(const float4*)(sH2e + k * SHS + 4 * tm);
        ulonglong2 u2 = *(const ulonglong2*)(sUW2 + (256 + k) * 16 + 4 * tn);
        unsigned long long s0, s1, s2, s3;
        SPLAT2(s0, a.x); SPLAT2(s1, a.y); SPLAT2(s2, a.z); SPLAT2(s3, a.w);
        FMA2(acc2[0][0], s0, u2.x); FMA2(acc2[0][1], s0, u2.y);
        FMA2(acc2[1][0], s1, u2.x); FMA2(acc2[1][1], s1, u2.y);
        FMA2(acc2[2][0], s2, u2.x); FMA2(acc2[2][1], s2, u2.y);
        FMA2(acc2[3][0], s3, u2.x); FMA2(acc2[3][1], s3, u2.y);
      }
#pragma unroll
      for (int r = 0; r < 4; r++) {
        float4 v;
        v.x = __uint_as_float((unsigned)(acc2[r][0] & 0xffffffffu));
        v.y = __uint_as_float((unsigned)(acc2[r][0] >> 32));
        v.z = __uint_as_float((unsigned)(acc2[r][1] & 0xffffffffu));
        v.w = __uint_as_float((unsigned)(acc2[r][1] >> 32));
        *(float4*)(sZp2 + (q * 32 + 4 * tm + r) * ZP2S + 4 * tn) = v;
      }
    }
    __syncthreads();

    // ---- epilogues ----
    if (t < TSTEPS) {
      float z[4];
#pragma unroll
      for (int g = 0; g < 4; g++) {
        float s = b1g[g];
#pragma unroll
        for (int q2 = 0; q2 < 8; q2++) s += sZp1[(q2 * 32 + bl) * ZPS + g * 8 + uu];
        z[g] = s;
      }
      float ig = 1.f / (1.f + __expf(-z[0]));
      float fg = 1.f / (1.f + __expf(-z[1]));
      float gg = fmaxf(z[2], 0.f);
      float og = 1.f / (1.f + __expf(-z[3]));
      c1 = fg * c1 + ig * gg;
      float h = og * fmaxf(c1, 0.f);
      g_hseq1[(size_t)(t + 1) * UN1 * BATCH + (size_t)u_g * BATCH + b_g] = h;
    }
    if (t >= 1 && tid < 128) {
      float z[4];
#pragma unroll
      for (int g = 0; g < 4; g++) {
        float s = b2g[g];
#pragma unroll
        for (int q2 = 0; q2 < 8; q2++) s += sZp2[(q2 * 32 + bl) * ZP2S + g * 4 + uu2];
        z[g] = s;
      }
      float ig = 1.f / (1.f + __expf(-z[0]));
      float fg = 1.f / (1.f + __expf(-z[1]));
      float gg = fmaxf(z[2], 0.f);
      float og = 1.f / (1.f + __expf(-z[3]));
      c2 = fg * c2 + ig * gg;
      float h = og * fmaxf(c2, 0.f);
      if (t < TSTEPS)
        g_hseq2[(size_t)t * UN2 * BATCH + (size_t)u_g2 * BATCH + b_g] = h;
      else
        out_last[b_g * UN2 + u_g2] = h;
    }
    __syncthreads();   // all h stores done before release

    // ---- arrive (release covers CTA's stores via bar.sync causality) ----
    if (tid == 0 && t < TSTEPS)
      asm volatile("red.release.gpu.global.add.u32 [%0], %1;" :: "l"(bar), "r"(1u));

    // ---- stage sX for t+1 while peers arrive ----
    if (t + 1 < TSTEPS) {
      for (int i = tid; i < 512; i += 256) {
        int bb = i >> 4, f4 = (i & 15) << 2;
        float4 v = *(const float4*)(x + (size_t)(b0 + bb) * TSTEPS * FEAT
                                      + (size_t)(t + 1) * FEAT + f4);
        sX[(f4 + 0) * SHS + bb] = v.x;
        sX[(f4 + 1) * SHS + bb] = v.y;
        sX[(f4 + 2) * SHS + bb] = v.z;
        sX[(f4 + 3) * SHS + bb] = v.w;
      }
    }
  }

  // ---- exit: last CTA of bg resets counters for next graph replay ----
  __syncthreads();
  if (tid == 0) {
    __threadfence();
    if (atomicAdd(exitc, 1u) + 1u == 32u) {
      *bar = 0u;
      *exitc = 0u;
    }
  }
}

// ---------------- launch --------------------------------------------------------
extern "C" void kernel_launch(void* const* d_in, const int* in_sizes, int n_in,
                              void* d_out, int out_size) {
  const float* x   = (const float*)d_in[0];
  const float* W1  = (const float*)d_in[1];
  const float* U1m = (const float*)d_in[2];
  const float* b1  = (const float*)d_in[3];
  const float* W2  = (const float*)d_in[4];
  const float* U2m = (const float*)d_in[5];
  const float* b2  = (const float*)d_in[6];
  float* out = (float*)d_out;

  constexpr int SMEM = (256 * 32 + 64 * 32 + 384 * 16 + 256 * 36 + 128 * 36 +
                        64 * 36 + 256 * 34 + 256 * 20) * 4;   // 185344 B
  cudaFuncSetAttribute(lstm_fused, cudaFuncAttributeMaxDynamicSharedMemorySize, SMEM);

  lstm_fused<<<128, 256, SMEM>>>(x, W1, U1m, b1, W2, U2m, b2, out);
}